// round 2
// baseline (speedup 1.0000x reference)
#include <cuda_runtime.h>

#define B_SZ   256
#define T_SZ   2048
#define N_SZ   128
#define NPAIRS (B_SZ * T_SZ)   // 524288
#define SROW   133             // smem row stride (conflict-free: gcd(5,32)=1)

// Scratch (device globals — no allocation allowed)
__device__ __align__(16) float g_h[NPAIRS * 2];   // hidden, [t][b] float2 layout
__device__ __align__(16) float g_q0[N_SZ];        // Q[:,0]
__device__ __align__(16) float g_q1[N_SZ];        // Q[:,1]

// ---------------------------------------------------------------------------
// Phase 1: block 0 solves (I+A) z_r = e_r and forms q_r = (I-A) z_r;
//          blocks 1..2 run the 256 leaky-RNN recurrences.
// ---------------------------------------------------------------------------
__global__ void phase1_kernel(const float* __restrict__ u,
                              const float* __restrict__ matB,
                              const float* __restrict__ wIn,
                              const float* __restrict__ wRec) {
    if (blockIdx.x == 0) {
        // ----- Cayley solve: one CTA, 128 threads, row-parallel GE -----
        extern __shared__ float W[];          // [128][SROW], cols 0..127 = I+A, 128/129 = RHS
        __shared__ float s_inv, s_z0, s_z1;
        const int i = threadIdx.x;

        for (int j = 0; j < N_SZ; j++) {
            float a = matB[i * N_SZ + j] - matB[j * N_SZ + i];   // A = B - B^T
            W[i * SROW + j] = (i == j ? 1.0f : 0.0f) + a;        // I + A
        }
        W[i * SROW + 128] = (i == 0) ? 1.0f : 0.0f;  // e0
        W[i * SROW + 129] = (i == 1) ? 1.0f : 0.0f;  // e1
        __syncthreads();

        // Forward elimination (no pivoting: symmetric part of I+A is SPD)
        for (int k = 0; k < N_SZ; k++) {
            if (i == k) s_inv = 1.0f / W[k * SROW + k];
            __syncthreads();
            if (i > k) {
                float f = W[i * SROW + k] * s_inv;
                #pragma unroll 4
                for (int j = k + 1; j < 130; j++)
                    W[i * SROW + j] -= f * W[k * SROW + j];
            }
            __syncthreads();
        }

        // Back substitution on the 2 RHS columns
        for (int k = N_SZ - 1; k >= 0; k--) {
            if (i == k) {
                float inv = 1.0f / W[k * SROW + k];
                s_z0 = W[k * SROW + 128] * inv;
                s_z1 = W[k * SROW + 129] * inv;
            }
            __syncthreads();
            if (i < k) {
                float a = W[i * SROW + k];
                W[i * SROW + 128] = fmaf(-a, s_z0, W[i * SROW + 128]);
                W[i * SROW + 129] = fmaf(-a, s_z1, W[i * SROW + 129]);
            } else if (i == k) {
                W[i * SROW + 128] = s_z0;
                W[i * SROW + 129] = s_z1;
            }
            __syncthreads();
        }

        // q_r = (I - A) z_r
        float q0 = W[i * SROW + 128];
        float q1 = W[i * SROW + 129];
        for (int k = 0; k < N_SZ; k++) {
            float a  = matB[i * N_SZ + k] - matB[k * N_SZ + i];
            float z0 = W[k * SROW + 128];   // broadcast read
            float z1 = W[k * SROW + 129];
            q0 = fmaf(-a, z0, q0);
            q1 = fmaf(-a, z1, q1);
        }
        g_q0[i] = q0;
        g_q1[i] = q1;
    } else {
        // ----- Leaky RNN: one thread per sequence -----
        const int seq = (blockIdx.x - 1) * (int)blockDim.x + (int)threadIdx.x;
        if (seq >= B_SZ) return;

        // fold ALPHA=0.1 into the weights
        const float W00 = 0.1f * wRec[0], W01 = 0.1f * wRec[1];
        const float W10 = 0.1f * wRec[2], W11 = 0.1f * wRec[3];
        const float I00 = 0.1f * wIn[0], I01 = 0.1f * wIn[1], I02 = 0.1f * wIn[2];
        const float I10 = 0.1f * wIn[3], I11 = 0.1f * wIn[4], I12 = 0.1f * wIn[5];

        const float4* up = (const float4*)(u + (size_t)seq * T_SZ * 3);
        float2* hp = (float2*)g_h;

        float y0 = 0.0f, y1 = 0.0f;
        float4 a = up[0], b = up[1], c = up[2];   // 12 floats = 4 timesteps

        #define RNN_STEP(X0, X1, X2, TT)                                        \
            {                                                                   \
                float r0 = fmaxf(y0, 0.0f);                                     \
                float r1 = fmaxf(y1, 0.0f);                                     \
                float c0 = fmaf(I00, (X0), fmaf(I01, (X1), I02 * (X2)));        \
                float c1 = fmaf(I10, (X0), fmaf(I11, (X1), I12 * (X2)));        \
                y0 = fmaf(0.9f, y0, fmaf(W00, r0, fmaf(W01, r1, c0)));          \
                y1 = fmaf(0.9f, y1, fmaf(W10, r0, fmaf(W11, r1, c1)));          \
                hp[(TT) * B_SZ + seq] = make_float2(y0, y1);                    \
            }

        for (int t = 0; t < T_SZ; t += 4) {
            // software-pipeline next 4 timesteps' inputs (clamped at the tail)
            int nt = (t + 4 < T_SZ) ? (t + 4) : t;
            int nbase = (nt >> 2) * 3;
            float4 na = up[nbase + 0];
            float4 nb = up[nbase + 1];
            float4 nc = up[nbase + 2];

            RNN_STEP(a.x, a.y, a.z, t + 0);
            RNN_STEP(a.w, b.x, b.y, t + 1);
            RNN_STEP(b.z, b.w, c.x, t + 2);
            RNN_STEP(c.y, c.z, c.w, t + 3);

            a = na; b = nb; c = nc;
        }
        #undef RNN_STEP
    }
}

// ---------------------------------------------------------------------------
// Phase 2: out[b,t,j] = h0 * q0[j] + h1 * q1[j]
// One warp per (b,t): 32 lanes x float4 = 128 contiguous floats (coalesced).
// ---------------------------------------------------------------------------
__global__ void expand_kernel(float* __restrict__ out) {
    const int lane  = threadIdx.x & 31;
    const int warp  = ((int)blockIdx.x * (int)blockDim.x + (int)threadIdx.x) >> 5;
    const int nwarp = ((int)gridDim.x * (int)blockDim.x) >> 5;

    const float4 q0 = ((const float4*)g_q0)[lane];
    const float4 q1 = ((const float4*)g_q1)[lane];
    const float2* hp = (const float2*)g_h;
    float4* o = (float4*)out;

    for (int p = warp; p < NPAIRS; p += nwarp) {
        float2 h = hp[p];            // broadcast within warp
        int t = p >> 8;              // h stored [t][b]
        int b = p & (B_SZ - 1);
        size_t off = ((size_t)b * T_SZ + t) * 32 + lane;
        float4 v;
        v.x = fmaf(h.x, q0.x, h.y * q1.x);
        v.y = fmaf(h.x, q0.y, h.y * q1.y);
        v.z = fmaf(h.x, q0.z, h.y * q1.z);
        v.w = fmaf(h.x, q0.w, h.y * q1.w);
        __stcs(&o[off], v);          // streaming store: 256MB >> L2, don't pollute
    }
}

// ---------------------------------------------------------------------------
extern "C" void kernel_launch(void* const* d_in, const int* in_sizes, int n_in,
                              void* d_out, int out_size) {
    // Identify inputs by element count (robust to ordering):
    // u = 256*2048*3 = 1572864, matB = 128*128 = 16384, wIn = 6, wRec = 4
    const float *u = nullptr, *matB = nullptr, *wIn = nullptr, *wRec = nullptr;
    for (int i = 0; i < n_in; i++) {
        switch (in_sizes[i]) {
            case 1572864: u    = (const float*)d_in[i]; break;
            case 16384:   matB = (const float*)d_in[i]; break;
            case 6:       wIn  = (const float*)d_in[i]; break;
            case 4:       wRec = (const float*)d_in[i]; break;
        }
    }

    const int smem = N_SZ * SROW * (int)sizeof(float);  // 68096 B
    cudaFuncSetAttribute(phase1_kernel,
                         cudaFuncAttributeMaxDynamicSharedMemorySize, smem);

    // block 0: solve;  blocks 1..2: 256 RNN sequences (128 threads each)
    phase1_kernel<<<3, 128, smem>>>(u, matB, wIn, wRec);

    // expand: 148*8 blocks x 256 threads
    expand_kernel<<<1184, 256>>>((float*)d_out);
}

// round 3
// speedup vs baseline: 1.2840x; 1.2840x over previous
#include <cuda_runtime.h>

#define B_SZ   256
#define T_SZ   2048
#define N_SZ   128
#define NPAIRS (B_SZ * T_SZ)   // 524288

// W: 128 rows x 132 floats (cols 0..127 = I+A, 128/129 = RHS, 130/131 pad)
// 132 floats = 33 float4 per row; 33 mod 8 = 1 (odd) => conflict-free LDS.128
#define WROW   132
#define WROW4  33
#define BSROW  129   // padded matB staging rows (conflict-free transposed reads)

// Scratch (device globals — no allocation allowed)
__device__ __align__(16) float g_h[NPAIRS * 2];   // hidden, [t][b] float2 layout
__device__ __align__(16) float g_q0[N_SZ];        // Q[:,0]
__device__ __align__(16) float g_q1[N_SZ];        // Q[:,1]

__device__ __forceinline__ float fast_rcp(float x) {
    float r;
    asm("rcp.approx.f32 %0, %1;" : "=f"(r) : "f"(x));
    return r;
}

// ---------------------------------------------------------------------------
// Phase 1: block 0 solves (I+A) z_r = e_r and forms q_r = (I-A) z_r;
//          blocks 1..2 run the 256 leaky-RNN recurrences.
// ---------------------------------------------------------------------------
__global__ void phase1_kernel(const float* __restrict__ u,
                              const float* __restrict__ matB,
                              const float* __restrict__ wIn,
                              const float* __restrict__ wRec) {
    if (blockIdx.x == 0) {
        // ================= Cayley solve: 1 CTA, 128 threads =================
        extern __shared__ float smem[];
        float*  Wf = smem;                      // [128][132]
        float4* W4 = (float4*)smem;             // [128][33]
        float*  Bs = smem + N_SZ * WROW;        // [128][129]
        __shared__ float z0s[N_SZ], z1s[N_SZ];
        const int i = threadIdx.x;

        // ---- stage matB into smem, coalesced float4 loads ----
        for (int idx = i; idx < N_SZ * 32; idx += N_SZ) {
            int r = idx >> 5, c4 = idx & 31;
            float4 v = ((const float4*)matB)[r * 32 + c4];
            float* dst = Bs + r * BSROW + c4 * 4;
            dst[0] = v.x; dst[1] = v.y; dst[2] = v.z; dst[3] = v.w;
        }
        __syncthreads();

        // ---- build augmented [I+A | e0 e1] ----
        {
            float* wr = Wf + i * WROW;
            #pragma unroll 4
            for (int j = 0; j < N_SZ; j++) {
                float a = Bs[i * BSROW + j] - Bs[j * BSROW + i];
                wr[j] = (i == j ? 1.0f : 0.0f) + a;
            }
            wr[128] = (i == 0) ? 1.0f : 0.0f;
            wr[129] = (i == 1) ? 1.0f : 0.0f;
            wr[130] = 0.0f; wr[131] = 0.0f;
        }

        // ---- forward elimination: ONE barrier per pivot, float4 updates ----
        for (int k = 0; k < N_SZ; k++) {
            __syncthreads();
            float rinv = fast_rcp(Wf[k * WROW + k]);     // every thread, broadcast read
            if (i > k) {
                float f = Wf[i * WROW + k] * rinv;
                float4*       wr = W4 + i * WROW4;
                const float4* pr = W4 + k * WROW4;
                #pragma unroll 4
                for (int g = (k >> 2); g < WROW4; g++) {
                    float4 a = wr[g];
                    float4 p = pr[g];
                    a.x = fmaf(-f, p.x, a.x);
                    a.y = fmaf(-f, p.y, a.y);
                    a.z = fmaf(-f, p.z, a.z);
                    a.w = fmaf(-f, p.w, a.w);
                    wr[g] = a;
                }
            }
        }

        // ---- back substitution (2 RHS), one barrier per step ----
        for (int k = N_SZ - 1; k >= 0; k--) {
            __syncthreads();
            float rinv = fast_rcp(Wf[k * WROW + k]);
            float zk0 = Wf[k * WROW + 128] * rinv;       // broadcast reads
            float zk1 = Wf[k * WROW + 129] * rinv;
            if (i < k) {
                float a = Wf[i * WROW + k];
                Wf[i * WROW + 128] = fmaf(-a, zk0, Wf[i * WROW + 128]);
                Wf[i * WROW + 129] = fmaf(-a, zk1, Wf[i * WROW + 129]);
            } else if (i == k) {
                z0s[k] = zk0;
                z1s[k] = zk1;
            }
        }
        __syncthreads();

        // ---- q_r = (I - A) z_r ----
        float q0 = z0s[i], q1 = z1s[i];
        #pragma unroll 4
        for (int k = 0; k < N_SZ; k++) {
            float a = Bs[i * BSROW + k] - Bs[k * BSROW + i];
            q0 = fmaf(-a, z0s[k], q0);
            q1 = fmaf(-a, z1s[k], q1);
        }
        g_q0[i] = q0;
        g_q1[i] = q1;
    } else {
        // ================= Leaky RNN: one thread per sequence ===============
        const int seq = (blockIdx.x - 1) * (int)blockDim.x + (int)threadIdx.x;
        if (seq >= B_SZ) return;

        // fold ALPHA=0.1 into the weights
        const float W00 = 0.1f * wRec[0], W01 = 0.1f * wRec[1];
        const float W10 = 0.1f * wRec[2], W11 = 0.1f * wRec[3];
        const float I00 = 0.1f * wIn[0], I01 = 0.1f * wIn[1], I02 = 0.1f * wIn[2];
        const float I10 = 0.1f * wIn[3], I11 = 0.1f * wIn[4], I12 = 0.1f * wIn[5];

        const float4* up = (const float4*)(u + (size_t)seq * T_SZ * 3);
        float2* hp = (float2*)g_h;

        float y0 = 0.0f, y1 = 0.0f;
        float4 a = up[0], b = up[1], c = up[2];   // 12 floats = 4 timesteps

        // 12-cycle dependent chain: a0=fmaf(0.9,y0,c0) || r=relu(y) ; then two fma
        #define RNN_STEP(X0, X1, X2, TT)                                        \
            {                                                                   \
                float c0 = fmaf(I00, (X0), fmaf(I01, (X1), I02 * (X2)));        \
                float c1 = fmaf(I10, (X0), fmaf(I11, (X1), I12 * (X2)));        \
                float a0 = fmaf(0.9f, y0, c0);                                  \
                float a1 = fmaf(0.9f, y1, c1);                                  \
                float r0 = fmaxf(y0, 0.0f);                                     \
                float r1 = fmaxf(y1, 0.0f);                                     \
                float t0 = fmaf(W00, r0, a0);                                   \
                float t1 = fmaf(W10, r0, a1);                                   \
                y0 = fmaf(W01, r1, t0);                                         \
                y1 = fmaf(W11, r1, t1);                                         \
                hp[(TT) * B_SZ + seq] = make_float2(y0, y1);                    \
            }

        for (int t = 0; t < T_SZ; t += 4) {
            int nt = (t + 4 < T_SZ) ? (t + 4) : t;
            int nbase = (nt >> 2) * 3;
            float4 na = up[nbase + 0];
            float4 nb = up[nbase + 1];
            float4 nc = up[nbase + 2];

            RNN_STEP(a.x, a.y, a.z, t + 0);
            RNN_STEP(a.w, b.x, b.y, t + 1);
            RNN_STEP(b.z, b.w, c.x, t + 2);
            RNN_STEP(c.y, c.z, c.w, t + 3);

            a = na; b = nb; c = nc;
        }
        #undef RNN_STEP
    }
}

// ---------------------------------------------------------------------------
// Phase 2: out[b,t,:] = h0 * q0[:] + h1 * q1[:]
// Warp task q = b*2048 + t (t fastest) -> consecutive warps write consecutive
// 2KB chunks => large sequential DRAM runs. 4 timesteps per warp.
// ---------------------------------------------------------------------------
__global__ void expand_kernel(float* __restrict__ out) {
    const int lane = threadIdx.x & 31;
    const int wid  = ((int)blockIdx.x * (int)blockDim.x + (int)threadIdx.x) >> 5;
    const int nw   = ((int)gridDim.x * (int)blockDim.x) >> 5;

    const float4 q0 = ((const float4*)g_q0)[lane];
    const float4 q1 = ((const float4*)g_q1)[lane];
    const float2* hp = (const float2*)g_h;
    float4* o = (float4*)out;

    const int ntask = NPAIRS / 4;   // 131072 warp-tasks of 4 timesteps each
    for (int task = wid; task < ntask; task += nw) {
        int q = task << 2;          // q = b*2048 + t, t multiple of 4
        int b = q >> 11;
        int t = q & (T_SZ - 1);

        float2 h0 = hp[(t + 0) * B_SZ + b];
        float2 h1 = hp[(t + 1) * B_SZ + b];
        float2 h2 = hp[(t + 2) * B_SZ + b];
        float2 h3 = hp[(t + 3) * B_SZ + b];

        size_t base = (size_t)q * 32 + lane;
        float4 v;
        v.x = fmaf(h0.x, q0.x, h0.y * q1.x);
        v.y = fmaf(h0.x, q0.y, h0.y * q1.y);
        v.z = fmaf(h0.x, q0.z, h0.y * q1.z);
        v.w = fmaf(h0.x, q0.w, h0.y * q1.w);
        __stcs(&o[base], v);
        v.x = fmaf(h1.x, q0.x, h1.y * q1.x);
        v.y = fmaf(h1.x, q0.y, h1.y * q1.y);
        v.z = fmaf(h1.x, q0.z, h1.y * q1.z);
        v.w = fmaf(h1.x, q0.w, h1.y * q1.w);
        __stcs(&o[base + 32], v);
        v.x = fmaf(h2.x, q0.x, h2.y * q1.x);
        v.y = fmaf(h2.x, q0.y, h2.y * q1.y);
        v.z = fmaf(h2.x, q0.z, h2.y * q1.z);
        v.w = fmaf(h2.x, q0.w, h2.y * q1.w);
        __stcs(&o[base + 64], v);
        v.x = fmaf(h3.x, q0.x, h3.y * q1.x);
        v.y = fmaf(h3.x, q0.y, h3.y * q1.y);
        v.z = fmaf(h3.x, q0.z, h3.y * q1.z);
        v.w = fmaf(h3.x, q0.w, h3.y * q1.w);
        __stcs(&o[base + 96], v);
    }
}

// ---------------------------------------------------------------------------
extern "C" void kernel_launch(void* const* d_in, const int* in_sizes, int n_in,
                              void* d_out, int out_size) {
    // Identify inputs by element count:
    // u = 1572864, matB = 16384, wIn = 6, wRec = 4
    const float *u = nullptr, *matB = nullptr, *wIn = nullptr, *wRec = nullptr;
    for (int i = 0; i < n_in; i++) {
        switch (in_sizes[i]) {
            case 1572864: u    = (const float*)d_in[i]; break;
            case 16384:   matB = (const float*)d_in[i]; break;
            case 6:       wIn  = (const float*)d_in[i]; break;
            case 4:       wRec = (const float*)d_in[i]; break;
        }
    }

    const int smem = (N_SZ * WROW + N_SZ * BSROW) * (int)sizeof(float); // 133632 B
    static int attr_set = 0;
    cudaFuncSetAttribute(phase1_kernel,
                         cudaFuncAttributeMaxDynamicSharedMemorySize, smem);
    (void)attr_set;

    // block 0: solve;  blocks 1..2: 256 RNN sequences (128 threads each)
    phase1_kernel<<<3, 128, smem>>>(u, matB, wIn, wRec);

    // expand: write-bandwidth bound
    expand_kernel<<<1184, 256>>>((float*)d_out);
}

// round 6
// speedup vs baseline: 1.9643x; 1.5299x over previous
#include <cuda_runtime.h>
#include <cstdint>
#include <stdint.h>

#define B_SZ   256
#define T_SZ   2048
#define N_SZ   128
#define NPAIRS (B_SZ * T_SZ)   // 524288

// Solve workspace: 128 rows x 132 floats (cols 0..127 = I+A, 128/129 = RHS)
#define WROW   132
#define WROW4  33
#define BSROW  129

// RNN staging ring: 3 chunks x 128 seqs x 25 float4 (24 used + 1 pad)
#define CT      32                  // timesteps per chunk
#define NCHUNK  (T_SZ / CT)         // 64
#define F4_PER_CHUNK 24             // 32 steps * 3 floats / 4
#define ROWF4   25                  // padded (conflict-free LDS.128)
#define RING_BYTES (3 * 128 * ROWF4 * 16)   // 153600

// Scratch (device globals — no allocation allowed)
__device__ __align__(16) float g_h[NPAIRS * 2];   // hidden, [t][b] float2 layout
__device__ __align__(16) float g_q0[N_SZ];        // Q[:,0]
__device__ __align__(16) float g_q1[N_SZ];        // Q[:,1]

__device__ __forceinline__ float fast_rcp(float x) {
    float r;
    asm("rcp.approx.f32 %0, %1;" : "=f"(r) : "f"(x));
    return r;
}

__device__ __forceinline__ void cp_async16(unsigned int dst_smem, const void* src) {
    asm volatile("cp.async.cg.shared.global [%0], [%1], 16;"
                 :: "r"(dst_smem), "l"(src) : "memory");
}
__device__ __forceinline__ void cp_commit() {
    asm volatile("cp.async.commit_group;" ::: "memory");
}
template <int N>
__device__ __forceinline__ void cp_wait() {
    asm volatile("cp.async.wait_group %0;" :: "n"(N) : "memory");
}

// loader: issue one 32-timestep chunk (24 cp.async per loader thread)
__device__ __forceinline__ void issue_chunk(int c, int l, unsigned int ring_u32,
                                            const float4* uc4, int seqBase) {
    int buf = c % 3;
    #pragma unroll
    for (int jj = 0; jj < F4_PER_CHUNK; jj++) {
        int idx = jj * 128 + l;
        int s = idx / F4_PER_CHUNK;
        int j = idx % F4_PER_CHUNK;
        unsigned int dst = ring_u32
            + (unsigned int)((buf * 128 + s) * ROWF4 + j) * 16u;
        const float4* src = uc4 + (size_t)(seqBase + s) * 1536
                                + (size_t)c * F4_PER_CHUNK + j;
        cp_async16(dst, src);
    }
    cp_commit();
}

// ---------------------------------------------------------------------------
// Phase 1 (256 threads/block):
//   block 0:      Cayley solve (threads 0..127 work, all barrier)
//   blocks 1..2:  leaky RNN — threads 0..127 compute (1 seq each),
//                 threads 128..255 stream u into a cp.async smem ring
// ---------------------------------------------------------------------------
__global__ void phase1_kernel(const float* __restrict__ u,
                              const float* __restrict__ matB,
                              const float* __restrict__ wIn,
                              const float* __restrict__ wRec) {
    extern __shared__ float smem[];
    const int tid = threadIdx.x;

    if (blockIdx.x == 0) {
        // ================= Cayley solve =================
        float*  Wf = smem;                      // [128][132]
        float4* W4 = (float4*)smem;             // [128][33]
        float*  Bs = smem + N_SZ * WROW;        // [128][129]
        __shared__ float z0s[N_SZ], z1s[N_SZ];
        const int i = tid;

        // stage matB (coalesced float4), all 256 threads
        for (int idx = tid; idx < N_SZ * 32; idx += 256) {
            int r = idx >> 5, c4 = idx & 31;
            float4 v = ((const float4*)matB)[r * 32 + c4];
            float* dst = Bs + r * BSROW + c4 * 4;
            dst[0] = v.x; dst[1] = v.y; dst[2] = v.z; dst[3] = v.w;
        }
        __syncthreads();

        // build augmented [I+A | e0 e1]
        if (i < N_SZ) {
            float* wr = Wf + i * WROW;
            #pragma unroll 4
            for (int j = 0; j < N_SZ; j++) {
                float a = Bs[i * BSROW + j] - Bs[j * BSROW + i];
                wr[j] = (i == j ? 1.0f : 0.0f) + a;
            }
            wr[128] = (i == 0) ? 1.0f : 0.0f;
            wr[129] = (i == 1) ? 1.0f : 0.0f;
            wr[130] = 0.0f; wr[131] = 0.0f;
        }

        // forward elimination: one barrier per pivot
        for (int k = 0; k < N_SZ; k++) {
            __syncthreads();
            if (i < N_SZ && i > k) {
                float rinv = fast_rcp(Wf[k * WROW + k]);
                float f = Wf[i * WROW + k] * rinv;
                float4*       wr = W4 + i * WROW4;
                const float4* pr = W4 + k * WROW4;
                #pragma unroll 4
                for (int g = (k >> 2); g < WROW4; g++) {
                    float4 a = wr[g];
                    float4 p = pr[g];
                    a.x = fmaf(-f, p.x, a.x);
                    a.y = fmaf(-f, p.y, a.y);
                    a.z = fmaf(-f, p.z, a.z);
                    a.w = fmaf(-f, p.w, a.w);
                    wr[g] = a;
                }
            }
        }

        // back substitution (2 RHS)
        for (int k = N_SZ - 1; k >= 0; k--) {
            __syncthreads();
            if (i < N_SZ) {
                float rinv = fast_rcp(Wf[k * WROW + k]);
                float zk0 = Wf[k * WROW + 128] * rinv;
                float zk1 = Wf[k * WROW + 129] * rinv;
                if (i < k) {
                    float a = Wf[i * WROW + k];
                    Wf[i * WROW + 128] = fmaf(-a, zk0, Wf[i * WROW + 128]);
                    Wf[i * WROW + 129] = fmaf(-a, zk1, Wf[i * WROW + 129]);
                } else if (i == k) {
                    z0s[k] = zk0;
                    z1s[k] = zk1;
                }
            }
        }
        __syncthreads();

        // q_r = (I - A) z_r
        if (i < N_SZ) {
            float q0 = z0s[i], q1 = z1s[i];
            #pragma unroll 4
            for (int k = 0; k < N_SZ; k++) {
                float a = Bs[i * BSROW + k] - Bs[k * BSROW + i];
                q0 = fmaf(-a, z0s[k], q0);
                q1 = fmaf(-a, z1s[k], q1);
            }
            g_q0[i] = q0;
            g_q1[i] = q1;
        }
    } else {
        // ================= Leaky RNN: warp-specialized =================
        const int seqBase = (blockIdx.x - 1) * 128;
        float4* ring = (float4*)smem;                    // [3][128][ROWF4]
        unsigned int ring_u32 = (unsigned int)__cvta_generic_to_shared(ring);
        const float4* uc4 = (const float4*)u;            // 1536 float4 per seq

        const bool isLoader = (tid >= 128);
        const int  l = tid & 127;

        // compute-thread coefficients (ALPHA folded in)
        float W00, W01, W10, W11, I00, I01, I02, I10, I11, I12;
        float y0 = 0.0f, y1 = 0.0f;
        float2* hp = (float2*)g_h;
        const int seq = seqBase + l;

        if (isLoader) {
            issue_chunk(0, l, ring_u32, uc4, seqBase);
            issue_chunk(1, l, ring_u32, uc4, seqBase);
        } else {
            W00 = 0.1f * wRec[0]; W01 = 0.1f * wRec[1];
            W10 = 0.1f * wRec[2]; W11 = 0.1f * wRec[3];
            I00 = 0.1f * wIn[0];  I01 = 0.1f * wIn[1];  I02 = 0.1f * wIn[2];
            I10 = 0.1f * wIn[3];  I11 = 0.1f * wIn[4];  I12 = 0.1f * wIn[5];
        }

        #define RNN_STEP(X0, X1, X2, TT)                                        \
            {                                                                   \
                float c0 = fmaf(I00, (X0), fmaf(I01, (X1), I02 * (X2)));        \
                float c1 = fmaf(I10, (X0), fmaf(I11, (X1), I12 * (X2)));        \
                float a0 = fmaf(0.9f, y0, c0);                                  \
                float a1 = fmaf(0.9f, y1, c1);                                  \
                float r0 = fmaxf(y0, 0.0f);                                     \
                float r1 = fmaxf(y1, 0.0f);                                     \
                float t0 = fmaf(W00, r0, a0);                                   \
                float t1 = fmaf(W10, r0, a1);                                   \
                y0 = fmaf(W01, r1, t0);                                         \
                y1 = fmaf(W11, r1, t1);                                         \
                hp[(TT) * B_SZ + seq] = make_float2(y0, y1);                    \
            }

        for (int c = 0; c < NCHUNK; c++) {
            if (isLoader) {
                if (c < NCHUNK - 1) cp_wait<1>(); else cp_wait<0>();
            }
            __syncthreads();   // chunk c visible to compute; buf (c-1)%3 free

            if (isLoader) {
                if (c + 2 < NCHUNK) issue_chunk(c + 2, l, ring_u32, uc4, seqBase);
            } else {
                const float4* row = ring + (size_t)((c % 3) * 128 + l) * ROWF4;
                int tbase = c * CT;
                #pragma unroll
                for (int g = 0; g < 8; g++) {          // 8 groups x 4 steps
                    float4 a = row[g * 3 + 0];
                    float4 b = row[g * 3 + 1];
                    float4 d = row[g * 3 + 2];
                    int t = tbase + g * 4;
                    RNN_STEP(a.x, a.y, a.z, t + 0);
                    RNN_STEP(a.w, b.x, b.y, t + 1);
                    RNN_STEP(b.z, b.w, d.x, t + 2);
                    RNN_STEP(d.y, d.z, d.w, t + 3);
                }
            }
        }
        #undef RNN_STEP
    }
}

// ---------------------------------------------------------------------------
// Phase 2: out[b,t,:] = h0 * q0[:] + h1 * q1[:]
// Warp task q = b*2048 + t (t fastest) -> sequential 2KB runs per warp task.
// ---------------------------------------------------------------------------
__global__ void __launch_bounds__(256, 8) expand_kernel(float* __restrict__ out) {
    const int lane = threadIdx.x & 31;
    const int wid  = ((int)blockIdx.x * (int)blockDim.x + (int)threadIdx.x) >> 5;
    const int nw   = ((int)gridDim.x * (int)blockDim.x) >> 5;

    const float4 q0 = ((const float4*)g_q0)[lane];
    const float4 q1 = ((const float4*)g_q1)[lane];
    const float2* hp = (const float2*)g_h;
    float4* o = (float4*)out;

    const int ntask = NPAIRS / 4;   // 131072 warp-tasks of 4 timesteps
    for (int task = wid; task < ntask; task += nw) {
        int q = task << 2;          // q = b*2048 + t
        int b = q >> 11;
        int t = q & (T_SZ - 1);

        float2 h0 = hp[(t + 0) * B_SZ + b];
        float2 h1 = hp[(t + 1) * B_SZ + b];
        float2 h2 = hp[(t + 2) * B_SZ + b];
        float2 h3 = hp[(t + 3) * B_SZ + b];

        size_t base = (size_t)q * 32 + lane;
        float4 v;
        v.x = fmaf(h0.x, q0.x, h0.y * q1.x);
        v.y = fmaf(h0.x, q0.y, h0.y * q1.y);
        v.z = fmaf(h0.x, q0.z, h0.y * q1.z);
        v.w = fmaf(h0.x, q0.w, h0.y * q1.w);
        __stcs(&o[base], v);
        v.x = fmaf(h1.x, q0.x, h1.y * q1.x);
        v.y = fmaf(h1.x, q0.y, h1.y * q1.y);
        v.z = fmaf(h1.x, q0.z, h1.y * q1.z);
        v.w = fmaf(h1.x, q0.w, h1.y * q1.w);
        __stcs(&o[base + 32], v);
        v.x = fmaf(h2.x, q0.x, h2.y * q1.x);
        v.y = fmaf(h2.x, q0.y, h2.y * q1.y);
        v.z = fmaf(h2.x, q0.z, h2.y * q1.z);
        v.w = fmaf(h2.x, q0.w, h2.y * q1.w);
        __stcs(&o[base + 64], v);
        v.x = fmaf(h3.x, q0.x, h3.y * q1.x);
        v.y = fmaf(h3.x, q0.y, h3.y * q1.y);
        v.z = fmaf(h3.x, q0.z, h3.y * q1.z);
        v.w = fmaf(h3.x, q0.w, h3.y * q1.w);
        __stcs(&o[base + 96], v);
    }
}

// ---------------------------------------------------------------------------
extern "C" void kernel_launch(void* const* d_in, const int* in_sizes, int n_in,
                              void* d_out, int out_size) {
    // Identify inputs by element count:
    // u = 1572864, matB = 16384, wIn = 6, wRec = 4
    const float *u = nullptr, *matB = nullptr, *wIn = nullptr, *wRec = nullptr;
    for (int i = 0; i < n_in; i++) {
        switch (in_sizes[i]) {
            case 1572864: u    = (const float*)d_in[i]; break;
            case 16384:   matB = (const float*)d_in[i]; break;
            case 6:       wIn  = (const float*)d_in[i]; break;
            case 4:       wRec = (const float*)d_in[i]; break;
        }
    }

    const int smem_solve = (N_SZ * WROW + N_SZ * BSROW) * (int)sizeof(float); // 133632
    const int smem = (RING_BYTES > smem_solve) ? RING_BYTES : smem_solve;     // 153600
    cudaFuncSetAttribute(phase1_kernel,
                         cudaFuncAttributeMaxDynamicSharedMemorySize, smem);

    // block 0: solve;  blocks 1..2: RNN (128 compute + 128 loader threads)
    phase1_kernel<<<3, 256, smem>>>(u, matB, wIn, wRec);

    // expand: write-bandwidth bound
    expand_kernel<<<1184, 256>>>((float*)d_out);
}